// round 3
// baseline (speedup 1.0000x reference)
#include <cuda_runtime.h>

// ---------------------------------------------------------------------------
// SSIM loss, single fused kernel.
// Reformulation: s = p+t, d = p-t. Blur 4 fields {s, d, s^2, d^2}:
//   mu_pt        = (mu_s^2 - mu_d^2)/4
//   mu_p^2+mu_t^2= (mu_s^2 + mu_d^2)/2
//   vs = blur(s^2)-mu_s^2 >= 0,  vd = blur(d^2)-mu_d^2 >= 0
//   sigma_pt     = (vs - vd)/4
//   sig_p^2+sig_t^2 = (vs + vd)/2
// Tile 32x64 per 256-thread block; float2-packed inputs, float4-packed
// horizontal-pass outputs; last block finalizes (no init/final launches).
// ---------------------------------------------------------------------------

#define TW 32
#define TH 64
#define INW 42
#define INH 74
#define SPITCH 43                 // float2 stride
#define HPITCH 33                 // float4 stride
#define SMEM_IN_BYTES (INH * SPITCH * 8)     // 25456
#define SMEM_H_BYTES  (INH * HPITCH * 16)    // 39072
#define SMEM_BYTES    (SMEM_IN_BYTES + SMEM_H_BYTES)

#define GW_INIT { \
    0.00102840f, 0.00759879f, 0.03600075f, 0.10936067f, 0.21300550f, \
    0.26601167f, \
    0.21300550f, 0.10936067f, 0.03600075f, 0.00759879f, 0.00102840f }

__device__ double g_sum;
__device__ unsigned int g_count;

__global__ __launch_bounds__(256, 3) void ssim_kernel(
    const float* __restrict__ pred, const float* __restrict__ tgt,
    float* __restrict__ out, float inv_n, unsigned int nblocks)
{
    constexpr float GW[11] = GW_INIT;

    extern __shared__ char smem_raw[];
    float2* s_in = (float2*)smem_raw;                       // [INH][SPITCH]
    float4* s_h  = (float4*)(smem_raw + SMEM_IN_BYTES);     // [INH][HPITCH]
    __shared__ float s_wsum[8];

    const int tid = threadIdx.x;
    const int gx0 = blockIdx.x * TW - 5;
    const int gy0 = blockIdx.y * TH - 5;
    const size_t po = (size_t)blockIdx.z << 18;   // * 512*512
    const float* pbase = pred + po;
    const float* tbase = tgt + po;

    // ---- load halo tile, pack (s, d) ----
    #pragma unroll 4
    for (int idx = tid; idx < INH * INW; idx += 256) {
        int r = idx / INW;
        int c = idx - r * INW;
        int gy = gy0 + r;
        int gx = gx0 + c;
        float p = 0.0f, t = 0.0f;
        if ((unsigned)gy < 512u && (unsigned)gx < 512u) {
            int g = (gy << 9) + gx;
            p = __ldg(pbase + g);
            t = __ldg(tbase + g);
        }
        s_in[r * SPITCH + c] = make_float2(p + t, p - t);
    }
    __syncthreads();

    // ---- horizontal 11-tap pass: 74 rows x 4 spans of 8 = 296 items ----
    for (int it = tid; it < INH * 4; it += 256) {
        const int r  = it >> 2;
        const int c0 = (it & 3) * 8;
        float a0[8], a1[8], a2[8], a3[8];
        #pragma unroll
        for (int j = 0; j < 8; j++) { a0[j]=0.f; a1[j]=0.f; a2[j]=0.f; a3[j]=0.f; }

        const float2* row = s_in + r * SPITCH + c0;
        #pragma unroll
        for (int k = 0; k < 18; k++) {
            float2 v = row[k];
            float ss = v.x * v.x;
            float dd = v.y * v.y;
            #pragma unroll
            for (int j = 0; j < 8; j++) {
                const int w = k - j;
                if (w >= 0 && w < 11) {
                    a0[j] = fmaf(GW[w], v.x, a0[j]);
                    a1[j] = fmaf(GW[w], v.y, a1[j]);
                    a2[j] = fmaf(GW[w], ss,  a2[j]);
                    a3[j] = fmaf(GW[w], dd,  a3[j]);
                }
            }
        }
        float4* hrow = s_h + r * HPITCH + c0;
        #pragma unroll
        for (int j = 0; j < 8; j++)
            hrow[j] = make_float4(a0[j], a1[j], a2[j], a3[j]);
    }
    __syncthreads();

    // ---- vertical 11-tap pass: each thread = 1 col x 8 rows ----
    const int col  = tid & 31;
    const int row0 = (tid >> 5) * 8;

    float vs_[8], vd_[8], vss[8], vdd[8];
    #pragma unroll
    for (int o = 0; o < 8; o++) { vs_[o]=0.f; vd_[o]=0.f; vss[o]=0.f; vdd[o]=0.f; }

    #pragma unroll
    for (int i = 0; i < 18; i++) {
        float4 h = s_h[(row0 + i) * HPITCH + col];
        #pragma unroll
        for (int o = 0; o < 8; o++) {
            const int w = i - o;
            if (w >= 0 && w < 11) {
                vs_[o] = fmaf(GW[w], h.x, vs_[o]);
                vd_[o] = fmaf(GW[w], h.y, vd_[o]);
                vss[o] = fmaf(GW[w], h.z, vss[o]);
                vdd[o] = fmaf(GW[w], h.w, vdd[o]);
            }
        }
    }

    // ---- SSIM map (scaled by 4 in num and den) + local sum ----
    float local = 0.0f;
    #pragma unroll
    for (int o = 0; o < 8; o++) {
        float mus2 = vs_[o] * vs_[o];
        float mud2 = vd_[o] * vd_[o];
        float vs = fmaxf(vss[o] - mus2, 0.0f);
        float vd = fmaxf(vdd[o] - mud2, 0.0f);
        float mu_pt4    = mus2 - mud2;   // 4*mu_pt
        float mpp_mtt2  = mus2 + mud2;   // 2*(mu_p^2+mu_t^2)
        float sig_pt4   = vs - vd;       // 4*sigma_pt
        float sig_sum2  = vs + vd;       // 2*(sig_p^2+sig_t^2)
        float num = (mu_pt4 + 2e-4f) * (sig_pt4 + 18e-4f);
        float den = (mpp_mtt2 + 2e-4f) * (sig_sum2 + 18e-4f);
        local += __fdividef(num, den);
    }

    // ---- block reduction ----
    #pragma unroll
    for (int off = 16; off; off >>= 1)
        local += __shfl_xor_sync(0xffffffffu, local, off);
    if ((tid & 31) == 0) s_wsum[tid >> 5] = local;
    __syncthreads();

    if (tid == 0) {
        float bs = 0.0f;
        #pragma unroll
        for (int i = 0; i < 8; i++) bs += s_wsum[i];
        atomicAdd(&g_sum, (double)bs);
        __threadfence();
        unsigned int done = atomicAdd(&g_count, 1u) + 1u;
        if (done == nblocks) {
            unsigned long long raw =
                atomicExch((unsigned long long*)&g_sum, 0ULL);
            out[0] = 1.0f - (float)__longlong_as_double(raw) * inv_n;
            atomicExch(&g_count, 0u);
        }
    }
}

extern "C" void kernel_launch(void* const* d_in, const int* in_sizes, int n_in,
                              void* d_out, int out_size)
{
    const float* pred = (const float*)d_in[0];
    const float* tgt  = (const float*)d_in[1];
    float* out = (float*)d_out;

    const int n_elems = in_sizes[0];            // B*C*H*W
    const int planes  = n_elems >> 18;          // / (512*512)

    cudaFuncSetAttribute(ssim_kernel,
                         cudaFuncAttributeMaxDynamicSharedMemorySize,
                         SMEM_BYTES);

    dim3 grid(512 / TW, 512 / TH, planes);
    unsigned int nblocks = grid.x * grid.y * grid.z;
    ssim_kernel<<<grid, 256, SMEM_BYTES>>>(pred, tgt, out,
                                           1.0f / (float)n_elems, nblocks);
}

// round 4
// speedup vs baseline: 1.2839x; 1.2839x over previous
#include <cuda_runtime.h>

// ---------------------------------------------------------------------------
// SSIM loss, single fused kernel. s = p+t, d = p-t; blur {s, d, s^2, d^2}:
//   4*mu_pt = mu_s^2 - mu_d^2          2*(mu_p^2+mu_t^2) = mu_s^2 + mu_d^2
//   vs = blur(s^2)-mu_s^2 (>=0), vd = blur(d^2)-mu_d^2 (>=0)
//   4*sigma_pt = vs - vd               2*(sig_p^2+sig_t^2) = vs + vd
// Tile 32x32 / 256 threads. float2-packed inputs, float4-packed h-results.
// One h-item per thread (static offsets); row-major thread mapping keeps all
// LDS.64/LDS.128 conflict-free (odd pitches). Last block finalizes.
// ---------------------------------------------------------------------------

#define TW 32
#define TH 32
#define INW 42
#define INH 42
#define SPITCH 43   // float2 units (odd -> conflict-free 8B access)
#define HPITCH 33   // float4 units (odd -> conflict-free 16B access)

#define GW_INIT { \
    0.00102840f, 0.00759879f, 0.03600075f, 0.10936067f, 0.21300550f, \
    0.26601167f, \
    0.21300550f, 0.10936067f, 0.03600075f, 0.00759879f, 0.00102840f }

__device__ double g_sum;
__device__ unsigned int g_count;

__global__ __launch_bounds__(256, 4) void ssim_kernel(
    const float* __restrict__ pred, const float* __restrict__ tgt,
    float* __restrict__ out, float inv_n, unsigned int nblocks)
{
    constexpr float GW[11] = GW_INIT;

    __shared__ float2 s_in[INH * SPITCH];   // 14.45 KB
    __shared__ float4 s_h[INH * HPITCH];    // 22.18 KB
    __shared__ float  s_wsum[8];

    const int tid = threadIdx.x;
    const int gx0 = blockIdx.x * TW - 5;
    const int gy0 = blockIdx.y * TH - 5;
    const size_t po = (size_t)blockIdx.z << 18;   // * 512*512
    const float* pbase = pred + po;
    const float* tbase = tgt + po;

    // ---- load halo tile (42x42), pack (s, d) ----
    #pragma unroll
    for (int ii = 0; ii < 7; ii++) {
        int idx = tid + ii * 256;
        if (idx < INH * INW) {
            int r = idx / INW;
            int c = idx - r * INW;
            int gy = gy0 + r;
            int gx = gx0 + c;
            float p = 0.0f, t = 0.0f;
            if ((unsigned)gy < 512u && (unsigned)gx < 512u) {
                int g = (gy << 9) + gx;
                p = __ldg(pbase + g);
                t = __ldg(tbase + g);
            }
            s_in[r * SPITCH + c] = make_float2(p + t, p - t);
        }
    }
    __syncthreads();

    // ---- horizontal 11-tap pass: one item per thread (168 items) ----
    // item: row r (consecutive threads -> consecutive rows), span of 8 cols.
    if (tid < 168) {
        const int r    = tid & 63 ? tid % 42 : 0;   // placeholder removed below
        const int span = tid / 42;                   // 0..3
        const int row  = tid - span * 42;            // 0..41
        const int c0   = span * 8;
        (void)r;

        float a0[8], a1[8], a2[8], a3[8];
        #pragma unroll
        for (int j = 0; j < 8; j++) { a0[j]=0.f; a1[j]=0.f; a2[j]=0.f; a3[j]=0.f; }

        const float2* rowp = s_in + row * SPITCH + c0;
        #pragma unroll
        for (int k = 0; k < 18; k++) {
            float2 v = rowp[k];
            float ss = v.x * v.x;
            float dd = v.y * v.y;
            #pragma unroll
            for (int j = 0; j < 8; j++) {
                const int w = k - j;
                if (w >= 0 && w < 11) {
                    a0[j] = fmaf(GW[w], v.x, a0[j]);
                    a1[j] = fmaf(GW[w], v.y, a1[j]);
                    a2[j] = fmaf(GW[w], ss,  a2[j]);
                    a3[j] = fmaf(GW[w], dd,  a3[j]);
                }
            }
        }
        float4* hrow = s_h + row * HPITCH + c0;
        #pragma unroll
        for (int j = 0; j < 8; j++)
            hrow[j] = make_float4(a0[j], a1[j], a2[j], a3[j]);
    }
    __syncthreads();

    // ---- vertical 11-tap pass: each thread = 1 col x 4 output rows ----
    const int col  = tid & 31;
    const int row0 = (tid >> 5) * 4;

    float vs_[4], vd_[4], vss[4], vdd[4];
    #pragma unroll
    for (int o = 0; o < 4; o++) { vs_[o]=0.f; vd_[o]=0.f; vss[o]=0.f; vdd[o]=0.f; }

    const float4* hcol = s_h + row0 * HPITCH + col;
    #pragma unroll
    for (int i = 0; i < 14; i++) {
        float4 h = hcol[i * HPITCH];
        #pragma unroll
        for (int o = 0; o < 4; o++) {
            const int w = i - o;
            if (w >= 0 && w < 11) {
                vs_[o] = fmaf(GW[w], h.x, vs_[o]);
                vd_[o] = fmaf(GW[w], h.y, vd_[o]);
                vss[o] = fmaf(GW[w], h.z, vss[o]);
                vdd[o] = fmaf(GW[w], h.w, vdd[o]);
            }
        }
    }

    // ---- SSIM map (num & den both scaled by 4) + local sum ----
    float local = 0.0f;
    #pragma unroll
    for (int o = 0; o < 4; o++) {
        float mus2 = vs_[o] * vs_[o];
        float mud2 = vd_[o] * vd_[o];
        float vs = fmaxf(vss[o] - mus2, 0.0f);
        float vd = fmaxf(vdd[o] - mud2, 0.0f);
        float num = (mus2 - mud2 + 2e-4f) * (vs - vd + 18e-4f);
        float den = (mus2 + mud2 + 2e-4f) * (vs + vd + 18e-4f);
        local += __fdividef(num, den);
    }

    // ---- block reduction ----
    #pragma unroll
    for (int off = 16; off; off >>= 1)
        local += __shfl_xor_sync(0xffffffffu, local, off);
    if ((tid & 31) == 0) s_wsum[tid >> 5] = local;
    __syncthreads();

    if (tid == 0) {
        float bs = 0.0f;
        #pragma unroll
        for (int i = 0; i < 8; i++) bs += s_wsum[i];
        atomicAdd(&g_sum, (double)bs);
        __threadfence();
        unsigned int done = atomicAdd(&g_count, 1u) + 1u;
        if (done == nblocks) {
            unsigned long long raw =
                atomicExch((unsigned long long*)&g_sum, 0ULL);
            out[0] = 1.0f - (float)__longlong_as_double(raw) * inv_n;
            atomicExch(&g_count, 0u);
        }
    }
}

extern "C" void kernel_launch(void* const* d_in, const int* in_sizes, int n_in,
                              void* d_out, int out_size)
{
    const float* pred = (const float*)d_in[0];
    const float* tgt  = (const float*)d_in[1];
    float* out = (float*)d_out;

    const int n_elems = in_sizes[0];
    const int planes  = n_elems >> 18;

    dim3 grid(512 / TW, 512 / TH, planes);
    unsigned int nblocks = grid.x * grid.y * grid.z;
    ssim_kernel<<<grid, 256>>>(pred, tgt, out, 1.0f / (float)n_elems, nblocks);
}

// round 5
// speedup vs baseline: 1.2971x; 1.0103x over previous
#include <cuda_runtime.h>

// ---------------------------------------------------------------------------
// SSIM loss, single fused kernel. s = p+t, d = p-t; blur {s, d, s^2, d^2}:
//   4*mu_pt = mu_s^2 - mu_d^2          2*(mu_p^2+mu_t^2) = mu_s^2 + mu_d^2
//   vs = blur(s^2)-mu_s^2 (>=0), vd = blur(d^2)-mu_d^2 (>=0)
//   4*sigma_pt = vs - vd               2*(sig_p^2+sig_t^2) = vs + vd
// Tile 32x70, 320 threads:
//   h-pass: 80 halo rows x 4 spans of 8 = 320 items -> exactly 1 per thread
//   v-pass: 10 warps x 7 contiguous rows, col = lane
// Ragged bottom tile (rows >= 512) computed but masked out of the sum.
// ---------------------------------------------------------------------------

#define T    320
#define TW   32
#define TH   70
#define INW  42
#define INH  80
#define SPITCH 43   // float2 units (odd -> conflict-free)
#define HPITCH 33   // float4 units (odd -> conflict-free)
#define SMEM_IN_BYTES (INH * SPITCH * 8)     // 27520
#define SMEM_H_BYTES  (INH * HPITCH * 16)    // 42240
#define SMEM_BYTES    (SMEM_IN_BYTES + SMEM_H_BYTES)

#define GW_INIT { \
    0.00102840f, 0.00759879f, 0.03600075f, 0.10936067f, 0.21300550f, \
    0.26601167f, \
    0.21300550f, 0.10936067f, 0.03600075f, 0.00759879f, 0.00102840f }

__device__ double g_sum;
__device__ unsigned int g_count;

__global__ __launch_bounds__(T, 3) void ssim_kernel(
    const float* __restrict__ pred, const float* __restrict__ tgt,
    float* __restrict__ out, float inv_n, unsigned int nblocks)
{
    constexpr float GW[11] = GW_INIT;

    extern __shared__ char smem_raw[];
    float2* s_in = (float2*)smem_raw;                    // [INH][SPITCH]
    float4* s_h  = (float4*)(smem_raw + SMEM_IN_BYTES);  // [INH][HPITCH]
    __shared__ float s_wsum[10];

    const int tid = threadIdx.x;
    const int gx0 = blockIdx.x * TW - 5;
    const int gy0 = blockIdx.y * TH - 5;
    const size_t po = (size_t)blockIdx.z << 18;          // * 512*512
    const float* pbase = pred + po;
    const float* tbase = tgt + po;

    // ---- load halo tile (80 x 42), pack (s, d); zero pad outside image ----
    #pragma unroll
    for (int ii = 0; ii < 11; ii++) {
        int idx = tid + ii * T;
        if (idx < INH * INW) {
            int r = idx / INW;
            int c = idx - r * INW;
            int gy = gy0 + r;
            int gx = gx0 + c;
            float p = 0.0f, t = 0.0f;
            if ((unsigned)gy < 512u && (unsigned)gx < 512u) {
                int g = (gy << 9) + gx;
                p = __ldg(pbase + g);
                t = __ldg(tbase + g);
            }
            s_in[r * SPITCH + c] = make_float2(p + t, p - t);
        }
    }
    __syncthreads();

    // ---- horizontal 11-tap pass: exactly one item per thread ----
    {
        const int row  = tid % INH;        // consecutive tids -> consecutive rows
        const int span = tid / INH;        // 0..3
        const int c0   = span * 8;

        float a0[8], a1[8], a2[8], a3[8];
        #pragma unroll
        for (int j = 0; j < 8; j++) { a0[j]=0.f; a1[j]=0.f; a2[j]=0.f; a3[j]=0.f; }

        const float2* rowp = s_in + row * SPITCH + c0;
        #pragma unroll
        for (int k = 0; k < 18; k++) {
            float2 v = rowp[k];
            float ss = v.x * v.x;
            float dd = v.y * v.y;
            #pragma unroll
            for (int j = 0; j < 8; j++) {
                const int w = k - j;
                if (w >= 0 && w < 11) {
                    a0[j] = fmaf(GW[w], v.x, a0[j]);
                    a1[j] = fmaf(GW[w], v.y, a1[j]);
                    a2[j] = fmaf(GW[w], ss,  a2[j]);
                    a3[j] = fmaf(GW[w], dd,  a3[j]);
                }
            }
        }
        float4* hrow = s_h + row * HPITCH + c0;
        #pragma unroll
        for (int j = 0; j < 8; j++)
            hrow[j] = make_float4(a0[j], a1[j], a2[j], a3[j]);
    }
    __syncthreads();

    // ---- vertical 11-tap pass: warp w -> rows 7w..7w+6, col = lane ----
    const int col  = tid & 31;
    const int row0 = (tid >> 5) * 7;

    float vs_[7], vd_[7], vss[7], vdd[7];
    #pragma unroll
    for (int o = 0; o < 7; o++) { vs_[o]=0.f; vd_[o]=0.f; vss[o]=0.f; vdd[o]=0.f; }

    const float4* hcol = s_h + row0 * HPITCH + col;
    #pragma unroll
    for (int i = 0; i < 17; i++) {
        float4 h = hcol[i * HPITCH];
        #pragma unroll
        for (int o = 0; o < 7; o++) {
            const int w = i - o;
            if (w >= 0 && w < 11) {
                vs_[o] = fmaf(GW[w], h.x, vs_[o]);
                vd_[o] = fmaf(GW[w], h.y, vd_[o]);
                vss[o] = fmaf(GW[w], h.z, vss[o]);
                vdd[o] = fmaf(GW[w], h.w, vdd[o]);
            }
        }
    }

    // ---- SSIM map (num & den both scaled by 4); mask rows >= 512 ----
    const int gyout = blockIdx.y * TH + row0;
    float local = 0.0f;
    #pragma unroll
    for (int o = 0; o < 7; o++) {
        float mus2 = vs_[o] * vs_[o];
        float mud2 = vd_[o] * vd_[o];
        float vs = fmaxf(vss[o] - mus2, 0.0f);
        float vd = fmaxf(vdd[o] - mud2, 0.0f);
        float num = (mus2 - mud2 + 2e-4f) * (vs - vd + 18e-4f);
        float den = (mus2 + mud2 + 2e-4f) * (vs + vd + 18e-4f);
        float v = __fdividef(num, den);
        if (gyout + o < 512) local += v;
    }

    // ---- block reduction ----
    #pragma unroll
    for (int off = 16; off; off >>= 1)
        local += __shfl_xor_sync(0xffffffffu, local, off);
    if ((tid & 31) == 0) s_wsum[tid >> 5] = local;
    __syncthreads();

    if (tid == 0) {
        float bs = 0.0f;
        #pragma unroll
        for (int i = 0; i < 10; i++) bs += s_wsum[i];
        atomicAdd(&g_sum, (double)bs);
        __threadfence();
        unsigned int done = atomicAdd(&g_count, 1u) + 1u;
        if (done == nblocks) {
            unsigned long long raw =
                atomicExch((unsigned long long*)&g_sum, 0ULL);
            out[0] = 1.0f - (float)__longlong_as_double(raw) * inv_n;
            atomicExch(&g_count, 0u);
        }
    }
}

extern "C" void kernel_launch(void* const* d_in, const int* in_sizes, int n_in,
                              void* d_out, int out_size)
{
    const float* pred = (const float*)d_in[0];
    const float* tgt  = (const float*)d_in[1];
    float* out = (float*)d_out;

    const int n_elems = in_sizes[0];
    const int planes  = n_elems >> 18;

    cudaFuncSetAttribute(ssim_kernel,
                         cudaFuncAttributeMaxDynamicSharedMemorySize,
                         SMEM_BYTES);

    dim3 grid(512 / TW, (512 + TH - 1) / TH, planes);
    unsigned int nblocks = grid.x * grid.y * grid.z;
    ssim_kernel<<<grid, T, SMEM_BYTES>>>(pred, tgt, out,
                                         1.0f / (float)n_elems, nblocks);
}

// round 6
// speedup vs baseline: 1.3772x; 1.0617x over previous
#include <cuda_runtime.h>

// ---------------------------------------------------------------------------
// SSIM loss, single fused kernel, packed f32x2 math.
// s = p+t, d = p-t; blur {s, d, s^2, d^2} (pairs (s,d) and (s^2,d^2) live in
// one 64-bit register each; every conv step is one fma.rn.f32x2 = 2 FMAs):
//   4*mu_pt = mu_s^2 - mu_d^2          2*(mu_p^2+mu_t^2) = mu_s^2 + mu_d^2
//   vs = blur(s^2)-mu_s^2 (>=0), vd = blur(d^2)-mu_d^2 (>=0)
//   4*sigma_pt = vs - vd               2*(sig_p^2+sig_t^2) = vs + vd
// Tile 32x70, 320 threads: h-pass = 80 rows x 4 spans (1 item/thread);
// v-pass = 10 warps x 7 rows. Ragged bottom rows masked from the sum.
// ---------------------------------------------------------------------------

#define T    320
#define TW   32
#define TH   70
#define INW  42
#define INH  80
#define SPITCH 43   // b64 units (odd -> conflict-free)
#define HPITCH 33   // 16B units (odd -> conflict-free)
#define SMEM_IN_BYTES (INH * SPITCH * 8)     // 27520
#define SMEM_H_BYTES  (INH * HPITCH * 16)    // 42240
#define SMEM_BYTES    (SMEM_IN_BYTES + SMEM_H_BYTES)

#define GW_INIT { \
    0.00102840f, 0.00759879f, 0.03600075f, 0.10936067f, 0.21300550f, \
    0.26601167f, \
    0.21300550f, 0.10936067f, 0.03600075f, 0.00759879f, 0.00102840f }

typedef unsigned long long u64;

__device__ __forceinline__ u64 pack2(float lo, float hi) {
    u64 r;
    asm("mov.b64 %0, {%1, %2};" : "=l"(r)
        : "r"(__float_as_uint(lo)), "r"(__float_as_uint(hi)));
    return r;
}
__device__ __forceinline__ u64 bcast2(float x) { return pack2(x, x); }
__device__ __forceinline__ void unpack2(u64 v, float& lo, float& hi) {
    unsigned a, b;
    asm("mov.b64 {%0, %1}, %2;" : "=r"(a), "=r"(b) : "l"(v));
    lo = __uint_as_float(a);
    hi = __uint_as_float(b);
}
__device__ __forceinline__ u64 fma2(u64 a, u64 b, u64 c) {
    u64 d;
    asm("fma.rn.f32x2 %0, %1, %2, %3;" : "=l"(d) : "l"(a), "l"(b), "l"(c));
    return d;
}
__device__ __forceinline__ u64 mul2(u64 a, u64 b) {
    u64 d;
    asm("mul.rn.f32x2 %0, %1, %2;" : "=l"(d) : "l"(a), "l"(b));
    return d;
}

__device__ double g_sum;
__device__ unsigned int g_count;

__global__ __launch_bounds__(T, 3) void ssim_kernel(
    const float* __restrict__ pred, const float* __restrict__ tgt,
    float* __restrict__ out, float inv_n, unsigned int nblocks)
{
    constexpr float GW[11] = GW_INIT;

    extern __shared__ char smem_raw[];
    u64*        s_in = (u64*)smem_raw;                         // [INH][SPITCH]
    ulonglong2* s_h  = (ulonglong2*)(smem_raw + SMEM_IN_BYTES); // [INH][HPITCH]
    __shared__ float s_wsum[10];

    const int tid = threadIdx.x;
    const int gx0 = blockIdx.x * TW - 5;
    const int gy0 = blockIdx.y * TH - 5;
    const size_t po = (size_t)blockIdx.z << 18;                // * 512*512
    const float* pbase = pred + po;
    const float* tbase = tgt + po;

    // ---- load halo tile (80 x 42), pack (s, d); zero pad outside image ----
    {
        int r = tid / INW;          // one division total
        int c = tid - r * INW;
        #pragma unroll
        for (int ii = 0; ii < 11; ii++) {
            if (r < INH) {
                int gy = gy0 + r;
                int gx = gx0 + c;
                float p = 0.0f, t = 0.0f;
                if ((unsigned)gy < 512u && (unsigned)gx < 512u) {
                    int g = (gy << 9) + gx;
                    p = __ldg(pbase + g);
                    t = __ldg(tbase + g);
                }
                s_in[r * SPITCH + c] = pack2(p + t, p - t);
            }
            // advance by 320 = 7*42 + 26
            r += 7; c += 26;
            if (c >= INW) { c -= INW; r += 1; }
        }
    }
    __syncthreads();

    // ---- packed weights (6 unique values after symmetry) ----
    u64 W[11];
    #pragma unroll
    for (int w = 0; w < 11; w++) W[w] = bcast2(GW[w]);

    // ---- horizontal 11-tap pass: exactly one item per thread ----
    {
        const int row  = tid % INH;   // consecutive tids -> consecutive rows
        const int span = tid / INH;   // 0..3
        const int c0   = span * 8;

        u64 a01[8], a23[8];
        const u64 z = 0ULL;
        #pragma unroll
        for (int j = 0; j < 8; j++) { a01[j] = z; a23[j] = z; }

        const u64* rowp = s_in + row * SPITCH + c0;
        #pragma unroll
        for (int k = 0; k < 18; k++) {
            u64 v  = rowp[k];          // (s, d)
            u64 sq = mul2(v, v);       // (s^2, d^2)
            #pragma unroll
            for (int j = 0; j < 8; j++) {
                const int w = k - j;
                if (w >= 0 && w < 11) {
                    a01[j] = fma2(W[w], v,  a01[j]);
                    a23[j] = fma2(W[w], sq, a23[j]);
                }
            }
        }
        ulonglong2* hrow = s_h + row * HPITCH + c0;
        #pragma unroll
        for (int j = 0; j < 8; j++)
            hrow[j] = make_ulonglong2(a01[j], a23[j]);
    }
    __syncthreads();

    // ---- vertical 11-tap pass: warp w -> rows 7w..7w+6, col = lane ----
    const int col  = tid & 31;
    const int row0 = (tid >> 5) * 7;

    u64 m01[7], m23[7];
    #pragma unroll
    for (int o = 0; o < 7; o++) { m01[o] = 0ULL; m23[o] = 0ULL; }

    const ulonglong2* hcol = s_h + row0 * HPITCH + col;
    #pragma unroll
    for (int i = 0; i < 17; i++) {
        ulonglong2 h = hcol[i * HPITCH];
        #pragma unroll
        for (int o = 0; o < 7; o++) {
            const int w = i - o;
            if (w >= 0 && w < 11) {
                m01[o] = fma2(W[w], h.x, m01[o]);
                m23[o] = fma2(W[w], h.y, m23[o]);
            }
        }
    }

    // ---- SSIM map (num & den both scaled by 4); mask rows >= 512 ----
    const int gyout = blockIdx.y * TH + row0;
    float local = 0.0f;
    #pragma unroll
    for (int o = 0; o < 7; o++) {
        float mus, mud, bss, bdd;
        unpack2(m01[o], mus, mud);
        unpack2(m23[o], bss, bdd);
        float mus2 = mus * mus;
        float mud2 = mud * mud;
        float vs = fmaxf(bss - mus2, 0.0f);
        float vd = fmaxf(bdd - mud2, 0.0f);
        float num = (mus2 - mud2 + 2e-4f) * (vs - vd + 18e-4f);
        float den = (mus2 + mud2 + 2e-4f) * (vs + vd + 18e-4f);
        float v = __fdividef(num, den);
        if (gyout + o < 512) local += v;
    }

    // ---- block reduction ----
    #pragma unroll
    for (int off = 16; off; off >>= 1)
        local += __shfl_xor_sync(0xffffffffu, local, off);
    if ((tid & 31) == 0) s_wsum[tid >> 5] = local;
    __syncthreads();

    if (tid == 0) {
        float bs = 0.0f;
        #pragma unroll
        for (int i = 0; i < 10; i++) bs += s_wsum[i];
        atomicAdd(&g_sum, (double)bs);
        __threadfence();
        unsigned int done = atomicAdd(&g_count, 1u) + 1u;
        if (done == nblocks) {
            unsigned long long raw =
                atomicExch((unsigned long long*)&g_sum, 0ULL);
            out[0] = 1.0f - (float)__longlong_as_double(raw) * inv_n;
            atomicExch(&g_count, 0u);
        }
    }
}

extern "C" void kernel_launch(void* const* d_in, const int* in_sizes, int n_in,
                              void* d_out, int out_size)
{
    const float* pred = (const float*)d_in[0];
    const float* tgt  = (const float*)d_in[1];
    float* out = (float*)d_out;

    const int n_elems = in_sizes[0];
    const int planes  = n_elems >> 18;

    cudaFuncSetAttribute(ssim_kernel,
                         cudaFuncAttributeMaxDynamicSharedMemorySize,
                         SMEM_BYTES);

    dim3 grid(512 / TW, (512 + TH - 1) / TH, planes);
    unsigned int nblocks = grid.x * grid.y * grid.z;
    ssim_kernel<<<grid, T, SMEM_BYTES>>>(pred, tgt, out,
                                         1.0f / (float)n_elems, nblocks);
}

// round 7
// speedup vs baseline: 1.4438x; 1.0484x over previous
#include <cuda_runtime.h>

// ---------------------------------------------------------------------------
// SSIM loss, single fused kernel, packed f32x2 math.
// s = p+t, d = p-t; blur {s, d, s^2, d^2}; pairs (s,d),(s^2,d^2) in one b64
// register each -> every conv step is one fma.rn.f32x2 (2 FMAs).
//   4*mu_pt = mu_s^2 - mu_d^2          2*(mu_p^2+mu_t^2) = mu_s^2 + mu_d^2
//   vs = blur(s^2)-mu_s^2 (>=0), vd = blur(d^2)-mu_d^2 (>=0)
//   4*sigma_pt = vs - vd               2*(sig_p^2+sig_t^2) = vs + vd
// Tile 32x54, 256 threads: h-pass = 64 halo rows x 4 spans = 256 items,
// exactly one per thread; v-pass = 8 warps x 7 rows (rows >= 54 masked,
// LDS row index clamped to stay in-bounds). Last block finalizes.
// ---------------------------------------------------------------------------

#define T    256
#define TW   32
#define TH   54
#define INW  42
#define INH  64
#define SPITCH 43   // b64 units (odd -> conflict-free)
#define HPITCH 33   // 16B units (odd -> conflict-free)
#define SMEM_IN_BYTES (INH * SPITCH * 8)     // 22016
#define SMEM_H_BYTES  (INH * HPITCH * 16)    // 33792
#define SMEM_BYTES    (SMEM_IN_BYTES + SMEM_H_BYTES)

#define GW_INIT { \
    0.00102840f, 0.00759879f, 0.03600075f, 0.10936067f, 0.21300550f, \
    0.26601167f, \
    0.21300550f, 0.10936067f, 0.03600075f, 0.00759879f, 0.00102840f }

typedef unsigned long long u64;

__device__ __forceinline__ u64 pack2(float lo, float hi) {
    u64 r;
    asm("mov.b64 %0, {%1, %2};" : "=l"(r)
        : "r"(__float_as_uint(lo)), "r"(__float_as_uint(hi)));
    return r;
}
__device__ __forceinline__ void unpack2(u64 v, float& lo, float& hi) {
    unsigned a, b;
    asm("mov.b64 {%0, %1}, %2;" : "=r"(a), "=r"(b) : "l"(v));
    lo = __uint_as_float(a);
    hi = __uint_as_float(b);
}
__device__ __forceinline__ u64 fma2(u64 a, u64 b, u64 c) {
    u64 d;
    asm("fma.rn.f32x2 %0, %1, %2, %3;" : "=l"(d) : "l"(a), "l"(b), "l"(c));
    return d;
}
__device__ __forceinline__ u64 mul2(u64 a, u64 b) {
    u64 d;
    asm("mul.rn.f32x2 %0, %1, %2;" : "=l"(d) : "l"(a), "l"(b));
    return d;
}

__device__ double g_sum;
__device__ unsigned int g_count;

__global__ __launch_bounds__(T, 4) void ssim_kernel(
    const float* __restrict__ pred, const float* __restrict__ tgt,
    float* __restrict__ out, float inv_n, unsigned int nblocks)
{
    constexpr float GW[11] = GW_INIT;

    extern __shared__ char smem_raw[];
    u64*        s_in = (u64*)smem_raw;                          // [INH][SPITCH]
    ulonglong2* s_h  = (ulonglong2*)(smem_raw + SMEM_IN_BYTES); // [INH][HPITCH]
    __shared__ float s_wsum[8];

    const int tid = threadIdx.x;
    const int gx0 = blockIdx.x * TW - 5;
    const int gy0 = blockIdx.y * TH - 5;
    const size_t po = (size_t)blockIdx.z << 18;                 // * 512*512
    const float* pbase = pred + po;
    const float* tbase = tgt + po;

    // ---- load halo tile (64 x 42), pack (s, d); zero pad outside image ----
    {
        int r = tid / INW;          // one division total
        int c = tid - r * INW;
        #pragma unroll
        for (int ii = 0; ii < 11; ii++) {
            if (r < INH) {
                int gy = gy0 + r;
                int gx = gx0 + c;
                float p = 0.0f, t = 0.0f;
                if ((unsigned)gy < 512u && (unsigned)gx < 512u) {
                    int g = (gy << 9) + gx;
                    p = __ldg(pbase + g);
                    t = __ldg(tbase + g);
                }
                s_in[r * SPITCH + c] = pack2(p + t, p - t);
            }
            // advance by 256 = 6*42 + 4
            r += 6; c += 4;
            if (c >= INW) { c -= INW; r += 1; }
        }
    }
    __syncthreads();

    // ---- packed weights: 6 unique registers (Gaussian symmetry) ----
    u64 W[6];
    #pragma unroll
    for (int w = 0; w < 6; w++) W[w] = pack2(GW[w], GW[w]);
    #define WSYM(w) W[(w) < 6 ? (w) : 10 - (w)]

    // ---- horizontal 11-tap pass: exactly one item per thread ----
    {
        const int row  = tid & (INH - 1);   // consecutive tids -> rows
        const int span = tid >> 6;          // 0..3
        const int c0   = span * 8;

        u64 a01[8], a23[8];
        #pragma unroll
        for (int j = 0; j < 8; j++) { a01[j] = 0ULL; a23[j] = 0ULL; }

        const u64* rowp = s_in + row * SPITCH + c0;
        #pragma unroll
        for (int k = 0; k < 18; k++) {
            u64 v  = rowp[k];          // (s, d)
            u64 sq = mul2(v, v);       // (s^2, d^2)
            #pragma unroll
            for (int j = 0; j < 8; j++) {
                const int w = k - j;
                if (w >= 0 && w < 11) {
                    a01[j] = fma2(WSYM(w), v,  a01[j]);
                    a23[j] = fma2(WSYM(w), sq, a23[j]);
                }
            }
        }
        ulonglong2* hrow = s_h + row * HPITCH + c0;
        #pragma unroll
        for (int j = 0; j < 8; j++)
            hrow[j] = make_ulonglong2(a01[j], a23[j]);
    }
    __syncthreads();

    // ---- vertical 11-tap pass: warp w -> rows 7w..7w+6, col = lane ----
    const int col  = tid & 31;
    const int row0 = (tid >> 5) * 7;

    u64 m01[7], m23[7];
    #pragma unroll
    for (int o = 0; o < 7; o++) { m01[o] = 0ULL; m23[o] = 0ULL; }

    #pragma unroll
    for (int i = 0; i < 17; i++) {
        int ri = row0 + i;
        ri = ri > INH - 1 ? INH - 1 : ri;   // clamp: stay in-bounds (masked rows)
        ulonglong2 h = s_h[ri * HPITCH + col];
        #pragma unroll
        for (int o = 0; o < 7; o++) {
            const int w = i - o;
            if (w >= 0 && w < 11) {
                m01[o] = fma2(WSYM(w), h.x, m01[o]);
                m23[o] = fma2(WSYM(w), h.y, m23[o]);
            }
        }
    }

    // ---- SSIM map (num & den both scaled by 4); mask invalid rows ----
    const int gyout = blockIdx.y * TH + row0;
    float local = 0.0f;
    #pragma unroll
    for (int o = 0; o < 7; o++) {
        float mus, mud, bss, bdd;
        unpack2(m01[o], mus, mud);
        unpack2(m23[o], bss, bdd);
        float mus2 = mus * mus;
        float mud2 = mud * mud;
        float vs = fmaxf(bss - mus2, 0.0f);
        float vd = fmaxf(bdd - mud2, 0.0f);
        float num = (mus2 - mud2 + 2e-4f) * (vs - vd + 18e-4f);
        float den = (mus2 + mud2 + 2e-4f) * (vs + vd + 18e-4f);
        float v = __fdividef(num, den);
        if (row0 + o < TH && gyout + o < 512) local += v;
    }

    // ---- block reduction ----
    #pragma unroll
    for (int off = 16; off; off >>= 1)
        local += __shfl_xor_sync(0xffffffffu, local, off);
    if ((tid & 31) == 0) s_wsum[tid >> 5] = local;
    __syncthreads();

    if (tid == 0) {
        float bs = 0.0f;
        #pragma unroll
        for (int i = 0; i < 8; i++) bs += s_wsum[i];
        atomicAdd(&g_sum, (double)bs);
        __threadfence();
        unsigned int done = atomicAdd(&g_count, 1u) + 1u;
        if (done == nblocks) {
            unsigned long long raw =
                atomicExch((unsigned long long*)&g_sum, 0ULL);
            out[0] = 1.0f - (float)__longlong_as_double(raw) * inv_n;
            atomicExch(&g_count, 0u);
        }
    }
}

extern "C" void kernel_launch(void* const* d_in, const int* in_sizes, int n_in,
                              void* d_out, int out_size)
{
    const float* pred = (const float*)d_in[0];
    const float* tgt  = (const float*)d_in[1];
    float* out = (float*)d_out;

    const int n_elems = in_sizes[0];
    const int planes  = n_elems >> 18;

    cudaFuncSetAttribute(ssim_kernel,
                         cudaFuncAttributeMaxDynamicSharedMemorySize,
                         SMEM_BYTES);

    dim3 grid(512 / TW, (512 + TH - 1) / TH, planes);
    unsigned int nblocks = grid.x * grid.y * grid.z;
    ssim_kernel<<<grid, T, SMEM_BYTES>>>(pred, tgt, out,
                                         1.0f / (float)n_elems, nblocks);
}

// round 8
// speedup vs baseline: 1.4449x; 1.0007x over previous
#include <cuda_runtime.h>

// ---------------------------------------------------------------------------
// SSIM loss, single fused kernel, packed f32x2 math, 5-blocks/SM geometry.
// s = p+t, d = p-t; blur {s, d, s^2, d^2}; (s,d),(s^2,d^2) in one b64 reg
// each -> every conv step is one fma.rn.f32x2 (2 FMAs).
//   4*mu_pt = mu_s^2 - mu_d^2          2*(mu_p^2+mu_t^2) = mu_s^2 + mu_d^2
//   vs = blur(s^2)-mu_s^2 (>=0), vd = blur(d^2)-mu_d^2 (>=0)
//   4*sigma_pt = vs - vd               2*(sig_p^2+sig_t^2) = vs + vd
// Tile 32x40, 256 threads, INH=50 halo rows:
//   h-pass: 200 items (row, 8-col span), computed as two 4-col halves to
//           keep live registers low (<=51 regs -> 5 blocks/SM)
//   v-pass: 8 warps x 5 rows, reads rows row0..row0+14 <= 49 (no clamp)
// Last block finalizes; bottom image rows masked.
// ---------------------------------------------------------------------------

#define T    256
#define TW   32
#define TH   40
#define INW  42
#define INH  50
#define SPITCH 43   // b64 units (odd -> conflict-free)
#define HPITCH 33   // 16B units (odd -> conflict-free)
#define SMEM_IN_BYTES (INH * SPITCH * 8)     // 17200
#define SMEM_H_BYTES  (INH * HPITCH * 16)    // 26400
#define SMEM_BYTES    (SMEM_IN_BYTES + SMEM_H_BYTES)   // 43600

#define GW_INIT { \
    0.00102840f, 0.00759879f, 0.03600075f, 0.10936067f, 0.21300550f, \
    0.26601167f, \
    0.21300550f, 0.10936067f, 0.03600075f, 0.00759879f, 0.00102840f }

typedef unsigned long long u64;

__device__ __forceinline__ u64 pack2(float lo, float hi) {
    u64 r;
    asm("mov.b64 %0, {%1, %2};" : "=l"(r)
        : "r"(__float_as_uint(lo)), "r"(__float_as_uint(hi)));
    return r;
}
__device__ __forceinline__ void unpack2(u64 v, float& lo, float& hi) {
    unsigned a, b;
    asm("mov.b64 {%0, %1}, %2;" : "=r"(a), "=r"(b) : "l"(v));
    lo = __uint_as_float(a);
    hi = __uint_as_float(b);
}
__device__ __forceinline__ u64 fma2(u64 a, u64 b, u64 c) {
    u64 d;
    asm("fma.rn.f32x2 %0, %1, %2, %3;" : "=l"(d) : "l"(a), "l"(b), "l"(c));
    return d;
}
__device__ __forceinline__ u64 mul2(u64 a, u64 b) {
    u64 d;
    asm("mul.rn.f32x2 %0, %1, %2;" : "=l"(d) : "l"(a), "l"(b));
    return d;
}

__device__ double g_sum;
__device__ unsigned int g_count;

__global__ __launch_bounds__(T, 5) void ssim_kernel(
    const float* __restrict__ pred, const float* __restrict__ tgt,
    float* __restrict__ out, float inv_n, unsigned int nblocks)
{
    constexpr float GW[11] = GW_INIT;

    extern __shared__ char smem_raw[];
    u64*        s_in = (u64*)smem_raw;                          // [INH][SPITCH]
    ulonglong2* s_h  = (ulonglong2*)(smem_raw + SMEM_IN_BYTES); // [INH][HPITCH]
    __shared__ float s_wsum[8];

    const int tid = threadIdx.x;
    const int gx0 = blockIdx.x * TW - 5;
    const int gy0 = blockIdx.y * TH - 5;
    const size_t po = (size_t)blockIdx.z << 18;                 // * 512*512
    const float* pbase = pred + po;
    const float* tbase = tgt + po;

    // ---- load halo tile (50 x 42), pack (s, d); zero pad outside image ----
    {
        int r = tid / INW;          // one division total
        int c = tid - r * INW;
        #pragma unroll
        for (int ii = 0; ii < 9; ii++) {
            if (r < INH) {
                int gy = gy0 + r;
                int gx = gx0 + c;
                float p = 0.0f, t = 0.0f;
                if ((unsigned)gy < 512u && (unsigned)gx < 512u) {
                    int g = (gy << 9) + gx;
                    p = __ldg(pbase + g);
                    t = __ldg(tbase + g);
                }
                s_in[r * SPITCH + c] = pack2(p + t, p - t);
            }
            // advance by 256 = 6*42 + 4
            r += 6; c += 4;
            if (c >= INW) { c -= INW; r += 1; }
        }
    }
    __syncthreads();

    // ---- packed weights: 6 unique registers (Gaussian symmetry) ----
    u64 W[6];
    #pragma unroll
    for (int w = 0; w < 6; w++) W[w] = pack2(GW[w], GW[w]);
    #define WSYM(w) W[(w) < 6 ? (w) : 10 - (w)]

    // ---- horizontal 11-tap pass: one (row, 8-col span) item per thread,
    //      computed as two 4-col halves to cap live registers ----
    if (tid < INH * 4) {
        const int row  = tid % INH;   // consecutive tids -> consecutive rows
        const int span = tid / INH;   // 0..3
        const int c0   = span * 8;

        const u64* rowp = s_in + row * SPITCH + c0;
        ulonglong2* hrow = s_h + row * HPITCH + c0;

        #pragma unroll
        for (int half = 0; half < 2; half++) {
            u64 a01[4], a23[4];
            #pragma unroll
            for (int j = 0; j < 4; j++) { a01[j] = 0ULL; a23[j] = 0ULL; }

            const u64* rp = rowp + half * 4;
            #pragma unroll
            for (int k = 0; k < 14; k++) {
                u64 v  = rp[k];           // (s, d)
                u64 sq = mul2(v, v);      // (s^2, d^2)
                #pragma unroll
                for (int j = 0; j < 4; j++) {
                    const int w = k - j;
                    if (w >= 0 && w < 11) {
                        a01[j] = fma2(WSYM(w), v,  a01[j]);
                        a23[j] = fma2(WSYM(w), sq, a23[j]);
                    }
                }
            }
            #pragma unroll
            for (int j = 0; j < 4; j++)
                hrow[half * 4 + j] = make_ulonglong2(a01[j], a23[j]);
        }
    }
    __syncthreads();

    // ---- vertical 11-tap pass: warp w -> rows 5w..5w+4, col = lane ----
    const int col  = tid & 31;
    const int row0 = (tid >> 5) * 5;

    u64 m01[5], m23[5];
    #pragma unroll
    for (int o = 0; o < 5; o++) { m01[o] = 0ULL; m23[o] = 0ULL; }

    const ulonglong2* hcol = s_h + row0 * HPITCH + col;
    #pragma unroll
    for (int i = 0; i < 15; i++) {
        ulonglong2 h = hcol[i * HPITCH];      // rows row0..row0+14 <= 49
        #pragma unroll
        for (int o = 0; o < 5; o++) {
            const int w = i - o;
            if (w >= 0 && w < 11) {
                m01[o] = fma2(WSYM(w), h.x, m01[o]);
                m23[o] = fma2(WSYM(w), h.y, m23[o]);
            }
        }
    }

    // ---- SSIM map (num & den both scaled by 4); mask rows >= 512 ----
    const int gyout = blockIdx.y * TH + row0;
    float local = 0.0f;
    #pragma unroll
    for (int o = 0; o < 5; o++) {
        float mus, mud, bss, bdd;
        unpack2(m01[o], mus, mud);
        unpack2(m23[o], bss, bdd);
        float mus2 = mus * mus;
        float mud2 = mud * mud;
        float vs = fmaxf(bss - mus2, 0.0f);
        float vd = fmaxf(bdd - mud2, 0.0f);
        float num = (mus2 - mud2 + 2e-4f) * (vs - vd + 18e-4f);
        float den = (mus2 + mud2 + 2e-4f) * (vs + vd + 18e-4f);
        float v = __fdividef(num, den);
        if (gyout + o < 512) local += v;
    }

    // ---- block reduction ----
    #pragma unroll
    for (int off = 16; off; off >>= 1)
        local += __shfl_xor_sync(0xffffffffu, local, off);
    if ((tid & 31) == 0) s_wsum[tid >> 5] = local;
    __syncthreads();

    if (tid == 0) {
        float bs = 0.0f;
        #pragma unroll
        for (int i = 0; i < 8; i++) bs += s_wsum[i];
        atomicAdd(&g_sum, (double)bs);
        __threadfence();
        unsigned int done = atomicAdd(&g_count, 1u) + 1u;
        if (done == nblocks) {
            unsigned long long raw =
                atomicExch((unsigned long long*)&g_sum, 0ULL);
            out[0] = 1.0f - (float)__longlong_as_double(raw) * inv_n;
            atomicExch(&g_count, 0u);
        }
    }
}

extern "C" void kernel_launch(void* const* d_in, const int* in_sizes, int n_in,
                              void* d_out, int out_size)
{
    const float* pred = (const float*)d_in[0];
    const float* tgt  = (const float*)d_in[1];
    float* out = (float*)d_out;

    const int n_elems = in_sizes[0];
    const int planes  = n_elems >> 18;

    cudaFuncSetAttribute(ssim_kernel,
                         cudaFuncAttributeMaxDynamicSharedMemorySize,
                         SMEM_BYTES);

    dim3 grid(512 / TW, (512 + TH - 1) / TH, planes);
    unsigned int nblocks = grid.x * grid.y * grid.z;
    ssim_kernel<<<grid, T, SMEM_BYTES>>>(pred, tgt, out,
                                         1.0f / (float)n_elems, nblocks);
}

// round 9
// speedup vs baseline: 1.5173x; 1.0501x over previous
#include <cuda_runtime.h>

// ---------------------------------------------------------------------------
// SSIM loss, single fused kernel, packed f32x2 math.
// s = p+t, d = p-t; blur {s, d, s^2, d^2}; (s,d),(s^2,d^2) in one b64 reg
// each -> every conv step is one fma.rn.f32x2 (2 FMAs).
//   4*mu_pt = mu_s^2 - mu_d^2          2*(mu_p^2+mu_t^2) = mu_s^2 + mu_d^2
//   vs = blur(s^2)-mu_s^2 (>=0), vd = blur(d^2)-mu_d^2 (>=0)
//   4*sigma_pt = vs - vd               2*(sig_p^2+sig_t^2) = vs + vd
// Tile 32x54, 256 threads, halo 64 rows x 44 cols (starts at 32*bx-6, even,
// so gmem loads are aligned float2 = 2 px/thread).
//   h-pass: 64 rows x 4 spans of 8 = 256 items, exactly one per thread
//   v-pass: 8 warps x 7 rows (clamped smem row index; extra rows masked)
// Last block finalizes.
// ---------------------------------------------------------------------------

#define T    256
#define TW   32
#define TH   54
#define INW  44
#define INH  64
#define SPITCH 45   // b64 units (odd -> conflict-free)
#define HPITCH 33   // 16B units (odd -> conflict-free)
#define SMEM_IN_BYTES (INH * SPITCH * 8)     // 23040
#define SMEM_H_BYTES  (INH * HPITCH * 16)    // 33792
#define SMEM_BYTES    (SMEM_IN_BYTES + SMEM_H_BYTES)   // 56832

#define GW_INIT { \
    0.00102840f, 0.00759879f, 0.03600075f, 0.10936067f, 0.21300550f, \
    0.26601167f, \
    0.21300550f, 0.10936067f, 0.03600075f, 0.00759879f, 0.00102840f }

typedef unsigned long long u64;

__device__ __forceinline__ u64 pack2(float lo, float hi) {
    u64 r;
    asm("mov.b64 %0, {%1, %2};" : "=l"(r)
        : "r"(__float_as_uint(lo)), "r"(__float_as_uint(hi)));
    return r;
}
__device__ __forceinline__ void unpack2(u64 v, float& lo, float& hi) {
    unsigned a, b;
    asm("mov.b64 {%0, %1}, %2;" : "=r"(a), "=r"(b) : "l"(v));
    lo = __uint_as_float(a);
    hi = __uint_as_float(b);
}
__device__ __forceinline__ u64 fma2(u64 a, u64 b, u64 c) {
    u64 d;
    asm("fma.rn.f32x2 %0, %1, %2, %3;" : "=l"(d) : "l"(a), "l"(b), "l"(c));
    return d;
}
__device__ __forceinline__ u64 mul2(u64 a, u64 b) {
    u64 d;
    asm("mul.rn.f32x2 %0, %1, %2;" : "=l"(d) : "l"(a), "l"(b));
    return d;
}

__device__ double g_sum;
__device__ unsigned int g_count;

__global__ __launch_bounds__(T, 4) void ssim_kernel(
    const float* __restrict__ pred, const float* __restrict__ tgt,
    float* __restrict__ out, float inv_n, unsigned int nblocks)
{
    constexpr float GW[11] = GW_INIT;

    extern __shared__ char smem_raw[];
    u64*        s_in = (u64*)smem_raw;                          // [INH][SPITCH]
    ulonglong2* s_h  = (ulonglong2*)(smem_raw + SMEM_IN_BYTES); // [INH][HPITCH]
    __shared__ float s_wsum[8];

    const int tid = threadIdx.x;
    const int gxh = blockIdx.x * TW - 6;       // halo x start (even!)
    const int gy0 = blockIdx.y * TH - 5;
    const size_t po = (size_t)blockIdx.z << 18;                 // * 512*512
    const float* pbase = pred + po;
    const float* tbase = tgt + po;

    // ---- load halo tile (64 x 44) as aligned float2 pairs; pack (s, d) ----
    {
        // 64 rows x 22 pairs = 1408 items; step 256 = 11*22 + 14
        int r  = tid / 22;          // one division total
        int c2 = tid - r * 22;
        #pragma unroll
        for (int ii = 0; ii < 6; ii++) {
            if (r < INH) {
                int gy  = gy0 + r;
                int gxp = gxh + c2 * 2;        // even; pair all-in or all-out
                float2 p = make_float2(0.0f, 0.0f);
                float2 t = make_float2(0.0f, 0.0f);
                if ((unsigned)gy < 512u && (unsigned)gxp < 512u) {
                    int g = (gy << 9) + gxp;
                    p = *(const float2*)(pbase + g);
                    t = *(const float2*)(tbase + g);
                }
                u64* dst = s_in + r * SPITCH + c2 * 2;
                dst[0] = pack2(p.x + t.x, p.x - t.x);
                dst[1] = pack2(p.y + t.y, p.y - t.y);
            }
            r += 11; c2 += 14;
            if (c2 >= 22) { c2 -= 22; r += 1; }
        }
    }
    __syncthreads();

    // ---- packed weights: 6 unique registers (Gaussian symmetry) ----
    u64 W[6];
    #pragma unroll
    for (int w = 0; w < 6; w++) W[w] = pack2(GW[w], GW[w]);
    #define WSYM(w) W[(w) < 6 ? (w) : 10 - (w)]

    // ---- horizontal 11-tap pass: exactly one 8-wide item per thread ----
    {
        const int row  = tid & (INH - 1);   // consecutive tids -> rows
        const int span = tid >> 6;          // 0..3
        const int c0   = span * 8;

        u64 a01[8], a23[8];
        #pragma unroll
        for (int j = 0; j < 8; j++) { a01[j] = 0ULL; a23[j] = 0ULL; }

        // output x = 32bx + c0 + j needs halo cols (c0 + j + 1) .. (c0 + j + 11)
        const u64* rowp = s_in + row * SPITCH + c0;
        #pragma unroll
        for (int k = 1; k <= 18; k++) {
            u64 v  = rowp[k];          // (s, d)
            u64 sq = mul2(v, v);       // (s^2, d^2)
            #pragma unroll
            for (int j = 0; j < 8; j++) {
                const int w = k - 1 - j;
                if (w >= 0 && w < 11) {
                    a01[j] = fma2(WSYM(w), v,  a01[j]);
                    a23[j] = fma2(WSYM(w), sq, a23[j]);
                }
            }
        }
        ulonglong2* hrow = s_h + row * HPITCH + c0;
        #pragma unroll
        for (int j = 0; j < 8; j++)
            hrow[j] = make_ulonglong2(a01[j], a23[j]);
    }
    __syncthreads();

    // ---- vertical 11-tap pass: warp w -> rows 7w..7w+6, col = lane ----
    const int col  = tid & 31;
    const int row0 = (tid >> 5) * 7;

    u64 m01[7], m23[7];
    #pragma unroll
    for (int o = 0; o < 7; o++) { m01[o] = 0ULL; m23[o] = 0ULL; }

    #pragma unroll
    for (int i = 0; i < 17; i++) {
        int ri = row0 + i;
        ri = ri > INH - 1 ? INH - 1 : ri;   // clamp (excess rows masked below)
        ulonglong2 h = s_h[ri * HPITCH + col];
        #pragma unroll
        for (int o = 0; o < 7; o++) {
            const int w = i - o;
            if (w >= 0 && w < 11) {
                m01[o] = fma2(WSYM(w), h.x, m01[o]);
                m23[o] = fma2(WSYM(w), h.y, m23[o]);
            }
        }
    }

    // ---- SSIM map (num & den both scaled by 4); mask invalid rows ----
    const int gyout = blockIdx.y * TH + row0;
    float local = 0.0f;
    #pragma unroll
    for (int o = 0; o < 7; o++) {
        float mus, mud, bss, bdd;
        unpack2(m01[o], mus, mud);
        unpack2(m23[o], bss, bdd);
        float mus2 = mus * mus;
        float mud2 = mud * mud;
        float vs = fmaxf(bss - mus2, 0.0f);
        float vd = fmaxf(bdd - mud2, 0.0f);
        float num = (mus2 - mud2 + 2e-4f) * (vs - vd + 18e-4f);
        float den = (mus2 + mud2 + 2e-4f) * (vs + vd + 18e-4f);
        float v = __fdividef(num, den);
        if (row0 + o < TH && gyout + o < 512) local += v;
    }

    // ---- block reduction ----
    #pragma unroll
    for (int off = 16; off; off >>= 1)
        local += __shfl_xor_sync(0xffffffffu, local, off);
    if ((tid & 31) == 0) s_wsum[tid >> 5] = local;
    __syncthreads();

    if (tid == 0) {
        float bs = 0.0f;
        #pragma unroll
        for (int i = 0; i < 8; i++) bs += s_wsum[i];
        atomicAdd(&g_sum, (double)bs);
        __threadfence();
        unsigned int done = atomicAdd(&g_count, 1u) + 1u;
        if (done == nblocks) {
            unsigned long long raw =
                atomicExch((unsigned long long*)&g_sum, 0ULL);
            out[0] = 1.0f - (float)__longlong_as_double(raw) * inv_n;
            atomicExch(&g_count, 0u);
        }
    }
}

extern "C" void kernel_launch(void* const* d_in, const int* in_sizes, int n_in,
                              void* d_out, int out_size)
{
    const float* pred = (const float*)d_in[0];
    const float* tgt  = (const float*)d_in[1];
    float* out = (float*)d_out;

    const int n_elems = in_sizes[0];
    const int planes  = n_elems >> 18;

    cudaFuncSetAttribute(ssim_kernel,
                         cudaFuncAttributeMaxDynamicSharedMemorySize,
                         SMEM_BYTES);

    dim3 grid(512 / TW, (512 + TH - 1) / TH, planes);
    unsigned int nblocks = grid.x * grid.y * grid.z;
    ssim_kernel<<<grid, T, SMEM_BYTES>>>(pred, tgt, out,
                                         1.0f / (float)n_elems, nblocks);
}